// round 13
// baseline (speedup 1.0000x reference)
#include <cuda_runtime.h>
#include <cuda_bf16.h>
#include <cstdint>
#include <math.h>

// Problem constants
#define BB 256
#define NN 128
#define PP 85
#define D_LIG 256
#define D_PROT 1280
#define D_ATTN 256
#define HH 4
#define DH 64

// ----------------------------------------------------------------------------
// Scratch (alloc-free rule: __device__ globals)
// ----------------------------------------------------------------------------
__device__ float g_Q[BB * NN * D_ATTN];
__device__ float g_K[BB * PP * D_ATTN];
__device__ float g_V[BB * PP * D_ATTN];

// bf16 split operands
__device__ __nv_bfloat16 g_lig_hi[BB * NN * D_LIG];
__device__ __nv_bfloat16 g_lig_lo[BB * NN * D_LIG];
__device__ __nv_bfloat16 g_prot_hi[BB * PP * D_PROT];
__device__ __nv_bfloat16 g_prot_lo[BB * PP * D_PROT];
__device__ __nv_bfloat16 g_ctx_hi[BB * NN * D_ATTN];
__device__ __nv_bfloat16 g_ctx_lo[BB * NN * D_ATTN];
// transposed + split weights: [N=256, K] K-major
__device__ __nv_bfloat16 g_Wqt_hi[D_ATTN * D_LIG];
__device__ __nv_bfloat16 g_Wqt_lo[D_ATTN * D_LIG];
__device__ __nv_bfloat16 g_Wkt_hi[D_ATTN * D_PROT];
__device__ __nv_bfloat16 g_Wkt_lo[D_ATTN * D_PROT];
__device__ __nv_bfloat16 g_Wvt_hi[D_ATTN * D_PROT];
__device__ __nv_bfloat16 g_Wvt_lo[D_ATTN * D_PROT];
__device__ __nv_bfloat16 g_Wot_hi[D_ATTN * D_ATTN];
__device__ __nv_bfloat16 g_Wot_lo[D_ATTN * D_ATTN];

// ----------------------------------------------------------------------------
// PTX helpers (baseline sm_80+ features only — compute_103-safe)
// ----------------------------------------------------------------------------
__device__ __forceinline__ uint32_t smem_u32(const void* p) {
    uint32_t a;
    asm("{ .reg .u64 t; cvta.to.shared.u64 t, %1; cvt.u32.u64 %0, t; }" : "=r"(a) : "l"(p));
    return a;
}

#define CP16(sa, ga) \
    asm volatile("cp.async.cg.shared.global [%0], [%1], 16;" :: "r"(sa), "l"(ga))
#define CP_COMMIT() asm volatile("cp.async.commit_group;")
#define CP_WAIT(n)  asm volatile("cp.async.wait_group %0;" :: "n"(n))

#define LDSM4(r, addr) \
    asm volatile("ldmatrix.sync.aligned.m8n8.x4.shared.b16 {%0,%1,%2,%3}, [%4];" \
        : "=r"((r)[0]), "=r"((r)[1]), "=r"((r)[2]), "=r"((r)[3]) : "r"(addr))

#define MMA16816(c, a, b0, b1) \
    asm volatile("mma.sync.aligned.m16n8k16.row.col.f32.bf16.bf16.f32 " \
        "{%0,%1,%2,%3}, {%4,%5,%6,%7}, {%8,%9}, {%0,%1,%2,%3};" \
        : "+f"((c)[0]), "+f"((c)[1]), "+f"((c)[2]), "+f"((c)[3]) \
        : "r"((a)[0]), "r"((a)[1]), "r"((a)[2]), "r"((a)[3]), "r"(b0), "r"(b1))

// ----------------------------------------------------------------------------
// HMMA bf16x3 GEMM: C[M,256] = A[M,K] @ Wt[256,K]^T  (fp32-equivalent)
// BM=128, BN=64, BK=32, 8 warps (4x2), warp tile 32x32, 3-stage cp.async pipeline.
// ----------------------------------------------------------------------------
#define GBM 128
#define GBN 64
#define GBK 32
#define ST_A_HI 0
#define ST_A_LO 8192
#define ST_B_HI 16384
#define ST_B_LO 20480
#define STAGE_BYTES 24576
#define NSTAGE 3
#define GT_SMEM (NSTAGE * STAGE_BYTES)   // 73728

__global__ void __launch_bounds__(256, 2)
gemm_mma_kernel(const __nv_bfloat16* __restrict__ Ahi,
                const __nv_bfloat16* __restrict__ Alo,
                const __nv_bfloat16* __restrict__ Bhi,   // [256, K] K-major
                const __nv_bfloat16* __restrict__ Blo,
                float* __restrict__ C, int K,
                const int* __restrict__ rmask)
{
    extern __shared__ char smem[];
    const uint32_t sbase = smem_u32(smem);
    const int tid = threadIdx.x;
    const int lane = tid & 31;
    const int warp = tid >> 5;
    const int warp_m = warp & 3;
    const int warp_n = warp >> 2;
    const int m0 = blockIdx.y * GBM;
    const int nblk = blockIdx.x * GBN;

    const int nch = K / GBK;    // >= 8 for all call sites

    float acc[2][4][4];
#pragma unroll
    for (int i = 0; i < 2; i++)
#pragma unroll
        for (int j = 0; j < 4; j++)
#pragma unroll
            for (int l = 0; l < 4; l++) acc[i][j][l] = 0.0f;

    auto fill = [&](int stage, int k0) {
        const uint32_t st = sbase + stage * STAGE_BYTES;
#pragma unroll
        for (int t = 0; t < 2; t++) {
            int i = tid + t * 256;
            int r = i >> 2, c = i & 3;
            uint32_t so = (uint32_t)(r * 64 + ((c ^ ((r >> 1) & 3)) << 4));
            const __nv_bfloat16* gh = Ahi + (size_t)(m0 + r) * K + k0 + c * 8;
            const __nv_bfloat16* gl = Alo + (size_t)(m0 + r) * K + k0 + c * 8;
            CP16(st + ST_A_HI + so, gh);
            CP16(st + ST_A_LO + so, gl);
        }
        {
            int r = tid >> 2, c = tid & 3;
            uint32_t so = (uint32_t)(r * 64 + ((c ^ ((r >> 1) & 3)) << 4));
            CP16(st + ST_B_HI + so, Bhi + (size_t)(nblk + r) * K + k0 + c * 8);
            CP16(st + ST_B_LO + so, Blo + (size_t)(nblk + r) * K + k0 + c * 8);
        }
        CP_COMMIT();
    };

    // prefetch two chunks ahead
    fill(0, 0);
    fill(1, GBK);

    int stage = 0;
    for (int ch = 0; ch < nch; ch++) {
        if (ch + 2 < nch) {
            fill((stage + 2) % NSTAGE, (ch + 2) * GBK);
            CP_WAIT(2);
        } else if (ch + 1 < nch) {
            CP_WAIT(1);
        } else {
            CP_WAIT(0);
        }
        __syncthreads();

        const uint32_t st = sbase + stage * STAGE_BYTES;
#pragma unroll
        for (int s = 0; s < 2; s++) {
            uint32_t afh[2][4], afl[2][4], bfh[2][4], bfl[2][4];
#pragma unroll
            for (int mt = 0; mt < 2; mt++) {
                int r = warp_m * 32 + mt * 16 + (lane & 15);
                int c = 2 * s + (lane >> 4);
                uint32_t so = (uint32_t)(r * 64 + ((c ^ ((r >> 1) & 3)) << 4));
                LDSM4(afh[mt], st + ST_A_HI + so);
                LDSM4(afl[mt], st + ST_A_LO + so);
            }
#pragma unroll
            for (int g = 0; g < 2; g++) {
                int r = warp_n * 32 + g * 16 + (lane & 15);
                int c = 2 * s + (lane >> 4);
                uint32_t so = (uint32_t)(r * 64 + ((c ^ ((r >> 1) & 3)) << 4));
                LDSM4(bfh[g], st + ST_B_HI + so);
                LDSM4(bfl[g], st + ST_B_LO + so);
            }
#pragma unroll
            for (int mt = 0; mt < 2; mt++)
#pragma unroll
                for (int g = 0; g < 2; g++) {
                    MMA16816(acc[mt][2 * g],     afh[mt], bfh[g][0], bfh[g][2]);
                    MMA16816(acc[mt][2 * g + 1], afh[mt], bfh[g][1], bfh[g][3]);
                    MMA16816(acc[mt][2 * g],     afh[mt], bfl[g][0], bfl[g][2]);
                    MMA16816(acc[mt][2 * g + 1], afh[mt], bfl[g][1], bfl[g][3]);
                    MMA16816(acc[mt][2 * g],     afl[mt], bfh[g][0], bfh[g][2]);
                    MMA16816(acc[mt][2 * g + 1], afl[mt], bfh[g][1], bfh[g][3]);
                }
        }
        __syncthreads();
        stage = (stage + 1) % NSTAGE;
    }

#pragma unroll
    for (int mt = 0; mt < 2; mt++) {
        int r0 = m0 + warp_m * 32 + mt * 16 + (lane >> 2);
        float mk0 = rmask ? (rmask[r0] ? 1.0f : 0.0f) : 1.0f;
        float mk1 = rmask ? (rmask[r0 + 8] ? 1.0f : 0.0f) : 1.0f;
#pragma unroll
        for (int nt = 0; nt < 4; nt++) {
            int col = nblk + warp_n * 32 + nt * 8 + 2 * (lane & 3);
            float2 o0, o1;
            o0.x = acc[mt][nt][0] * mk0;
            o0.y = acc[mt][nt][1] * mk0;
            o1.x = acc[mt][nt][2] * mk1;
            o1.y = acc[mt][nt][3] * mk1;
            *(float2*)&C[(size_t)r0 * D_ATTN + col] = o0;
            *(float2*)&C[(size_t)(r0 + 8) * D_ATTN + col] = o1;
        }
    }
}

// ----------------------------------------------------------------------------
// fp32 -> bf16 hi/lo split (vectorized by 4)
// ----------------------------------------------------------------------------
__global__ void split_kernel(const float4* __restrict__ x,
                             __nv_bfloat16* __restrict__ hi,
                             __nv_bfloat16* __restrict__ lo, int n4)
{
    int i = blockIdx.x * 256 + threadIdx.x;
    if (i >= n4) return;
    float4 v = x[i];
    __nv_bfloat16 h0 = __float2bfloat16(v.x);
    __nv_bfloat16 h1 = __float2bfloat16(v.y);
    __nv_bfloat16 h2 = __float2bfloat16(v.z);
    __nv_bfloat16 h3 = __float2bfloat16(v.w);
    __nv_bfloat16 l0 = __float2bfloat16(v.x - __bfloat162float(h0));
    __nv_bfloat16 l1 = __float2bfloat16(v.y - __bfloat162float(h1));
    __nv_bfloat16 l2 = __float2bfloat16(v.z - __bfloat162float(h2));
    __nv_bfloat16 l3 = __float2bfloat16(v.w - __bfloat162float(h3));
    uint2 oh, ol;
    oh.x = (uint32_t)__bfloat16_as_ushort(h0) | ((uint32_t)__bfloat16_as_ushort(h1) << 16);
    oh.y = (uint32_t)__bfloat16_as_ushort(h2) | ((uint32_t)__bfloat16_as_ushort(h3) << 16);
    ol.x = (uint32_t)__bfloat16_as_ushort(l0) | ((uint32_t)__bfloat16_as_ushort(l1) << 16);
    ol.y = (uint32_t)__bfloat16_as_ushort(l2) | ((uint32_t)__bfloat16_as_ushort(l3) << 16);
    *(uint2*)(hi + (size_t)i * 4) = oh;
    *(uint2*)(lo + (size_t)i * 4) = ol;
}

// transpose + split weights: W[K,N] -> Wt_hi/lo[N,K]
__global__ void splitT_kernel(const float* __restrict__ W,
                              __nv_bfloat16* __restrict__ hiT,
                              __nv_bfloat16* __restrict__ loT, int K, int N)
{
    int idx = blockIdx.x * 256 + threadIdx.x;
    if (idx >= K * N) return;
    int k = idx / N, n = idx % N;
    float v = W[idx];
    __nv_bfloat16 h = __float2bfloat16(v);
    __nv_bfloat16 l = __float2bfloat16(v - __bfloat162float(h));
    hiT[(size_t)n * K + k] = h;
    loT[(size_t)n * K + k] = l;
}

// ----------------------------------------------------------------------------
// Fused attention per (b, h): register-blocked, 8 query rows per warp-iteration.
// ----------------------------------------------------------------------------
#define ATT_F_KS 0
#define ATT_F_VS 5440
#define ATT_F_GT 10880
#define ATT_F_QG 10976
#define ATT_F_AR 15072
#define ATT_SMEM ((15072 + 5440) * 4)   // 82048 bytes

__global__ void __launch_bounds__(256, 2)
attention_kernel(const float* __restrict__ Q,
                 const float* __restrict__ K,
                 const float* __restrict__ V,
                 const float* __restrict__ conf,
                 const int* __restrict__ pmask,
                 const float* __restrict__ conf_w,
                 const float* __restrict__ conf_b,
                 float* __restrict__ attn_out,
                 __nv_bfloat16* __restrict__ ctx_hi,
                 __nv_bfloat16* __restrict__ ctx_lo)
{
    extern __shared__ float sf[];
    float* Ks = sf + ATT_F_KS;
    float* Vs = sf + ATT_F_VS;
    float* gt = sf + ATT_F_GT;
    float* Qg = sf + ATT_F_QG;
    float* Ar = sf + ATT_F_AR;

    const int h = blockIdx.x;
    const int b = blockIdx.y;
    const int tid = threadIdx.x;
    const int warp = tid >> 5;
    const int lane = tid & 31;

    if (tid < PP) {
        if (pmask[b * PP + tid]) {
            gt[tid] = -INFINITY;
        } else {
            float x = conf[b * PP + tid] * conf_w[0] + conf_b[0];
            float s = 1.0f / (1.0f + __expf(-x));
            gt[tid] = fmaxf(logf(s), -10.0f);
        }
    }
    for (int i = tid; i < PP * DH; i += 256) {
        int p = i / DH, d = i % DH;
        Ks[d * PP + p] = K[((size_t)(b * PP + p)) * D_ATTN + h * DH + d];
        Vs[i]          = V[((size_t)(b * PP + p)) * D_ATTN + h * DH + d];
    }
    __syncthreads();

    const bool v2 = lane < (PP - 64);
    const float g0 = gt[lane];
    const float g1 = gt[lane + 32];
    const float g2 = v2 ? gt[lane + 64] : -INFINITY;

    float* Qw = Qg + warp * 512;
    float* Aw = Ar + warp * 680;

#pragma unroll
    for (int grp = 0; grp < 2; grp++) {
        const int rbase = warp * 8 + grp * 64;

#pragma unroll
        for (int t = 0; t < 4; t++) {
            int idx = t * 128 + lane * 4;
            int r = idx >> 6, d = idx & 63;
            *(float4*)&Qw[idx] =
                *(const float4*)&Q[((size_t)(b * NN + rbase + r)) * D_ATTN + h * DH + d];
        }
        __syncwarp();

        float l[8][3];
#pragma unroll
        for (int r = 0; r < 8; r++) { l[r][0] = 0.0f; l[r][1] = 0.0f; l[r][2] = 0.0f; }

#pragma unroll 4
        for (int d = 0; d < DH; d++) {
            const float* kd = &Ks[d * PP];
            float k0 = kd[lane];
            float k1 = kd[lane + 32];
            float k2 = kd[v2 ? (lane + 64) : 0];
#pragma unroll
            for (int r = 0; r < 8; r++) {
                float q = Qw[r * 64 + d];
                l[r][0] = fmaf(q, k0, l[r][0]);
                l[r][1] = fmaf(q, k1, l[r][1]);
                l[r][2] = fmaf(q, k2, l[r][2]);
            }
        }

        float* aout = &attn_out[(((size_t)(b * HH + h)) * NN + rbase) * PP];
#pragma unroll
        for (int r = 0; r < 8; r++) {
            float l0 = l[r][0] * 0.125f + g0;
            float l1 = l[r][1] * 0.125f + g1;
            float l2 = v2 ? (l[r][2] * 0.125f + g2) : -INFINITY;

            float m = fmaxf(l0, fmaxf(l1, l2));
#pragma unroll
            for (int o = 16; o > 0; o >>= 1)
                m = fmaxf(m, __shfl_xor_sync(0xFFFFFFFF, m, o));

            float e0, e1, e2;
            if (isinf(m) && m < 0.0f) {
                e0 = e1 = e2 = 0.0f;
            } else {
                e0 = expf(l0 - m);
                e1 = expf(l1 - m);
                e2 = v2 ? expf(l2 - m) : 0.0f;
            }
            float s = e0 + e1 + e2;
#pragma unroll
            for (int o = 16; o > 0; o >>= 1)
                s += __shfl_xor_sync(0xFFFFFFFF, s, o);
            float inv = (s > 0.0f) ? (1.0f / s) : 0.0f;

            float a0 = e0 * inv, a1 = e1 * inv;
            Aw[r * PP + lane] = a0;
            aout[r * PP + lane] = a0;
            Aw[r * PP + lane + 32] = a1;
            aout[r * PP + lane + 32] = a1;
            if (v2) {
                float a2 = e2 * inv;
                Aw[r * PP + lane + 64] = a2;
                aout[r * PP + lane + 64] = a2;
            }
        }
        __syncwarp();

        float c0[8], c1[8];
#pragma unroll
        for (int r = 0; r < 8; r++) { c0[r] = 0.0f; c1[r] = 0.0f; }

#pragma unroll 5
        for (int p = 0; p < PP; p++) {
            float vv0 = Vs[p * DH + lane];
            float vv1 = Vs[p * DH + lane + 32];
#pragma unroll
            for (int r = 0; r < 8; r++) {
                float a = Aw[r * PP + p];
                c0[r] = fmaf(a, vv0, c0[r]);
                c1[r] = fmaf(a, vv1, c1[r]);
            }
        }

#pragma unroll
        for (int r = 0; r < 8; r++) {
            size_t base = ((size_t)(b * NN + rbase + r)) * D_ATTN + h * DH;
            __nv_bfloat16 h0 = __float2bfloat16(c0[r]);
            __nv_bfloat16 h1 = __float2bfloat16(c1[r]);
            ctx_hi[base + lane]      = h0;
            ctx_hi[base + lane + 32] = h1;
            ctx_lo[base + lane]      = __float2bfloat16(c0[r] - __bfloat162float(h0));
            ctx_lo[base + lane + 32] = __float2bfloat16(c1[r] - __bfloat162float(h1));
        }
        __syncwarp();
    }
}

// ----------------------------------------------------------------------------
extern "C" void kernel_launch(void* const* d_in, const int* in_sizes, int n_in,
                              void* d_out, int out_size)
{
    const float* ligand  = (const float*)d_in[0];
    const float* protein = (const float*)d_in[1];
    const float* conf    = (const float*)d_in[2];
    const int*   pmask   = (const int*)d_in[3];
    const int*   lmask   = (const int*)d_in[4];
    const float* Wq = (const float*)d_in[5];
    const float* Wk = (const float*)d_in[6];
    const float* Wv = (const float*)d_in[7];
    const float* Wo = (const float*)d_in[8];
    const float* conf_w = (const float*)d_in[9];
    const float* conf_b = (const float*)d_in[10];

    float* out_main = (float*)d_out;                          // (B,N,D_ATTN)
    float* out_attn = out_main + (size_t)BB * NN * D_ATTN;    // (B,H,N,P)

    float *Q, *Kb, *Vb;
    cudaGetSymbolAddress((void**)&Q,  g_Q);
    cudaGetSymbolAddress((void**)&Kb, g_K);
    cudaGetSymbolAddress((void**)&Vb, g_V);

    __nv_bfloat16 *lig_hi, *lig_lo, *prot_hi, *prot_lo, *ctx_hi, *ctx_lo;
    __nv_bfloat16 *Wqt_hi, *Wqt_lo, *Wkt_hi, *Wkt_lo, *Wvt_hi, *Wvt_lo, *Wot_hi, *Wot_lo;
    cudaGetSymbolAddress((void**)&lig_hi,  g_lig_hi);
    cudaGetSymbolAddress((void**)&lig_lo,  g_lig_lo);
    cudaGetSymbolAddress((void**)&prot_hi, g_prot_hi);
    cudaGetSymbolAddress((void**)&prot_lo, g_prot_lo);
    cudaGetSymbolAddress((void**)&ctx_hi,  g_ctx_hi);
    cudaGetSymbolAddress((void**)&ctx_lo,  g_ctx_lo);
    cudaGetSymbolAddress((void**)&Wqt_hi,  g_Wqt_hi);
    cudaGetSymbolAddress((void**)&Wqt_lo,  g_Wqt_lo);
    cudaGetSymbolAddress((void**)&Wkt_hi,  g_Wkt_hi);
    cudaGetSymbolAddress((void**)&Wkt_lo,  g_Wkt_lo);
    cudaGetSymbolAddress((void**)&Wvt_hi,  g_Wvt_hi);
    cudaGetSymbolAddress((void**)&Wvt_lo,  g_Wvt_lo);
    cudaGetSymbolAddress((void**)&Wot_hi,  g_Wot_hi);
    cudaGetSymbolAddress((void**)&Wot_lo,  g_Wot_lo);

    cudaFuncSetAttribute(gemm_mma_kernel,
                         cudaFuncAttributeMaxDynamicSharedMemorySize, GT_SMEM);
    cudaFuncSetAttribute(attention_kernel,
                         cudaFuncAttributeMaxDynamicSharedMemorySize, ATT_SMEM);

    // weight transpose + split (tiny)
    splitT_kernel<<<(D_LIG  * D_ATTN + 255) / 256, 256>>>(Wq, Wqt_hi, Wqt_lo, D_LIG,  D_ATTN);
    splitT_kernel<<<(D_PROT * D_ATTN + 255) / 256, 256>>>(Wk, Wkt_hi, Wkt_lo, D_PROT, D_ATTN);
    splitT_kernel<<<(D_PROT * D_ATTN + 255) / 256, 256>>>(Wv, Wvt_hi, Wvt_lo, D_PROT, D_ATTN);
    splitT_kernel<<<(D_ATTN * D_ATTN + 255) / 256, 256>>>(Wo, Wot_hi, Wot_lo, D_ATTN, D_ATTN);

    // activation splits
    {
        int n4 = (BB * NN * D_LIG) / 4;
        split_kernel<<<(n4 + 255) / 256, 256>>>((const float4*)ligand, lig_hi, lig_lo, n4);
    }
    {
        int n4 = (BB * PP * D_PROT) / 4;
        split_kernel<<<(n4 + 255) / 256, 256>>>((const float4*)protein, prot_hi, prot_lo, n4);
    }

    // Q = ligand @ Wq (masked rows zeroed)
    {
        dim3 grid(D_ATTN / GBN, (BB * NN) / GBM);
        gemm_mma_kernel<<<grid, 256, GT_SMEM>>>(lig_hi, lig_lo, Wqt_hi, Wqt_lo,
                                                Q, D_LIG, lmask);
    }
    // K, V = protein @ Wk/Wv
    {
        dim3 grid(D_ATTN / GBN, (BB * PP) / GBM);
        gemm_mma_kernel<<<grid, 256, GT_SMEM>>>(prot_hi, prot_lo, Wkt_hi, Wkt_lo,
                                                Kb, D_PROT, nullptr);
        gemm_mma_kernel<<<grid, 256, GT_SMEM>>>(prot_hi, prot_lo, Wvt_hi, Wvt_lo,
                                                Vb, D_PROT, nullptr);
    }
    // attention (writes attn probs + ctx bf16 hi/lo directly)
    {
        dim3 grid(HH, BB);
        attention_kernel<<<grid, 256, ATT_SMEM>>>(Q, Kb, Vb, conf, pmask, conf_w, conf_b,
                                                  out_attn, ctx_hi, ctx_lo);
    }
    // out = ctx @ Wo (masked rows zeroed)
    {
        dim3 grid(D_ATTN / GBN, (BB * NN) / GBM);
        gemm_mma_kernel<<<grid, 256, GT_SMEM>>>(ctx_hi, ctx_lo, Wot_hi, Wot_lo,
                                                out_main, D_ATTN, lmask);
    }
}

// round 14
// speedup vs baseline: 1.5464x; 1.5464x over previous
#include <cuda_runtime.h>
#include <cuda_bf16.h>
#include <cstdint>
#include <math.h>

// Problem constants
#define BB 256
#define NN 128
#define PP 85
#define D_LIG 256
#define D_PROT 1280
#define D_ATTN 256
#define HH 4
#define DH 64

// ----------------------------------------------------------------------------
// Scratch (alloc-free rule: __device__ globals)
// ----------------------------------------------------------------------------
__device__ float g_Q[BB * NN * D_ATTN];
__device__ float g_K[BB * PP * D_ATTN];
__device__ float g_V[BB * PP * D_ATTN];

// bf16 split operands
__device__ __nv_bfloat16 g_lig_hi[BB * NN * D_LIG];
__device__ __nv_bfloat16 g_lig_lo[BB * NN * D_LIG];
__device__ __nv_bfloat16 g_prot_hi[BB * PP * D_PROT];
__device__ __nv_bfloat16 g_prot_lo[BB * PP * D_PROT];
__device__ __nv_bfloat16 g_ctx_hi[BB * NN * D_ATTN];
__device__ __nv_bfloat16 g_ctx_lo[BB * NN * D_ATTN];
// transposed + split weights: [N=256, K] K-major
__device__ __nv_bfloat16 g_Wqt_hi[D_ATTN * D_LIG];
__device__ __nv_bfloat16 g_Wqt_lo[D_ATTN * D_LIG];
__device__ __nv_bfloat16 g_Wkt_hi[D_ATTN * D_PROT];
__device__ __nv_bfloat16 g_Wkt_lo[D_ATTN * D_PROT];
__device__ __nv_bfloat16 g_Wvt_hi[D_ATTN * D_PROT];
__device__ __nv_bfloat16 g_Wvt_lo[D_ATTN * D_PROT];
__device__ __nv_bfloat16 g_Wot_hi[D_ATTN * D_ATTN];
__device__ __nv_bfloat16 g_Wot_lo[D_ATTN * D_ATTN];

// ----------------------------------------------------------------------------
// PTX helpers (baseline sm_80+ features only — compute_103-safe)
// ----------------------------------------------------------------------------
__device__ __forceinline__ uint32_t smem_u32(const void* p) {
    uint32_t a;
    asm("{ .reg .u64 t; cvta.to.shared.u64 t, %1; cvt.u32.u64 %0, t; }" : "=r"(a) : "l"(p));
    return a;
}

#define CP16(sa, ga) \
    asm volatile("cp.async.cg.shared.global [%0], [%1], 16;" :: "r"(sa), "l"(ga))
#define CP_COMMIT() asm volatile("cp.async.commit_group;")
#define CP_WAIT(n)  asm volatile("cp.async.wait_group %0;" :: "n"(n))

#define LDSM4(r, addr) \
    asm volatile("ldmatrix.sync.aligned.m8n8.x4.shared.b16 {%0,%1,%2,%3}, [%4];" \
        : "=r"((r)[0]), "=r"((r)[1]), "=r"((r)[2]), "=r"((r)[3]) : "r"(addr))

#define MMA16816(c, a, b0, b1) \
    asm volatile("mma.sync.aligned.m16n8k16.row.col.f32.bf16.bf16.f32 " \
        "{%0,%1,%2,%3}, {%4,%5,%6,%7}, {%8,%9}, {%0,%1,%2,%3};" \
        : "+f"((c)[0]), "+f"((c)[1]), "+f"((c)[2]), "+f"((c)[3]) \
        : "r"((a)[0]), "r"((a)[1]), "r"((a)[2]), "r"((a)[3]), "r"(b0), "r"(b1))

// ----------------------------------------------------------------------------
// HMMA bf16x3 GEMM: C[M,256] = A[M,K] @ Wt[256,K]^T  (fp32-equivalent)
// BM=128, BN=64, BK=32, 8 warps (4x2), warp tile 32x32, double-buffered cp.async.
// (R11 configuration — best known; R12 KV-fusion and R13 3-stage both regressed.)
// ----------------------------------------------------------------------------
#define GBM 128
#define GBN 64
#define GBK 32
#define ST_A_HI 0
#define ST_A_LO 8192
#define ST_B_HI 16384
#define ST_B_LO 20480
#define STAGE_BYTES 24576
#define GT_SMEM (2 * STAGE_BYTES)   // 49152

__global__ void __launch_bounds__(256, 2)
gemm_mma_kernel(const __nv_bfloat16* __restrict__ Ahi,
                const __nv_bfloat16* __restrict__ Alo,
                const __nv_bfloat16* __restrict__ Bhi,   // [256, K] K-major
                const __nv_bfloat16* __restrict__ Blo,
                float* __restrict__ C, int K,
                const int* __restrict__ rmask)
{
    extern __shared__ char smem[];
    const uint32_t sbase = smem_u32(smem);
    const int tid = threadIdx.x;
    const int lane = tid & 31;
    const int warp = tid >> 5;
    const int warp_m = warp & 3;
    const int warp_n = warp >> 2;
    const int m0 = blockIdx.y * GBM;
    const int nblk = blockIdx.x * GBN;

    const int nch = K / GBK;

    float acc[2][4][4];
#pragma unroll
    for (int i = 0; i < 2; i++)
#pragma unroll
        for (int j = 0; j < 4; j++)
#pragma unroll
            for (int l = 0; l < 4; l++) acc[i][j][l] = 0.0f;

    auto fill = [&](int stage, int k0) {
        const uint32_t st = sbase + stage * STAGE_BYTES;
#pragma unroll
        for (int t = 0; t < 2; t++) {
            int i = tid + t * 256;
            int r = i >> 2, c = i & 3;
            uint32_t so = (uint32_t)(r * 64 + ((c ^ ((r >> 1) & 3)) << 4));
            const __nv_bfloat16* gh = Ahi + (size_t)(m0 + r) * K + k0 + c * 8;
            const __nv_bfloat16* gl = Alo + (size_t)(m0 + r) * K + k0 + c * 8;
            CP16(st + ST_A_HI + so, gh);
            CP16(st + ST_A_LO + so, gl);
        }
        {
            int r = tid >> 2, c = tid & 3;
            uint32_t so = (uint32_t)(r * 64 + ((c ^ ((r >> 1) & 3)) << 4));
            CP16(st + ST_B_HI + so, Bhi + (size_t)(nblk + r) * K + k0 + c * 8);
            CP16(st + ST_B_LO + so, Blo + (size_t)(nblk + r) * K + k0 + c * 8);
        }
        CP_COMMIT();
    };

    fill(0, 0);

    for (int ch = 0; ch < nch; ch++) {
        if (ch + 1 < nch) {
            fill((ch + 1) & 1, (ch + 1) * GBK);
            CP_WAIT(1);
        } else {
            CP_WAIT(0);
        }
        __syncthreads();

        const uint32_t st = sbase + (ch & 1) * STAGE_BYTES;
#pragma unroll
        for (int s = 0; s < 2; s++) {
            uint32_t afh[2][4], afl[2][4], bfh[2][4], bfl[2][4];
#pragma unroll
            for (int mt = 0; mt < 2; mt++) {
                int r = warp_m * 32 + mt * 16 + (lane & 15);
                int c = 2 * s + (lane >> 4);
                uint32_t so = (uint32_t)(r * 64 + ((c ^ ((r >> 1) & 3)) << 4));
                LDSM4(afh[mt], st + ST_A_HI + so);
                LDSM4(afl[mt], st + ST_A_LO + so);
            }
#pragma unroll
            for (int g = 0; g < 2; g++) {
                int r = warp_n * 32 + g * 16 + (lane & 15);
                int c = 2 * s + (lane >> 4);
                uint32_t so = (uint32_t)(r * 64 + ((c ^ ((r >> 1) & 3)) << 4));
                LDSM4(bfh[g], st + ST_B_HI + so);
                LDSM4(bfl[g], st + ST_B_LO + so);
            }
#pragma unroll
            for (int mt = 0; mt < 2; mt++)
#pragma unroll
                for (int g = 0; g < 2; g++) {
                    MMA16816(acc[mt][2 * g],     afh[mt], bfh[g][0], bfh[g][2]);
                    MMA16816(acc[mt][2 * g + 1], afh[mt], bfh[g][1], bfh[g][3]);
                    MMA16816(acc[mt][2 * g],     afh[mt], bfl[g][0], bfl[g][2]);
                    MMA16816(acc[mt][2 * g + 1], afh[mt], bfl[g][1], bfl[g][3]);
                    MMA16816(acc[mt][2 * g],     afl[mt], bfh[g][0], bfh[g][2]);
                    MMA16816(acc[mt][2 * g + 1], afl[mt], bfh[g][1], bfh[g][3]);
                }
        }
        __syncthreads();
    }

#pragma unroll
    for (int mt = 0; mt < 2; mt++) {
        int r0 = m0 + warp_m * 32 + mt * 16 + (lane >> 2);
        float mk0 = rmask ? (rmask[r0] ? 1.0f : 0.0f) : 1.0f;
        float mk1 = rmask ? (rmask[r0 + 8] ? 1.0f : 0.0f) : 1.0f;
#pragma unroll
        for (int nt = 0; nt < 4; nt++) {
            int col = nblk + warp_n * 32 + nt * 8 + 2 * (lane & 3);
            float2 o0, o1;
            o0.x = acc[mt][nt][0] * mk0;
            o0.y = acc[mt][nt][1] * mk0;
            o1.x = acc[mt][nt][2] * mk1;
            o1.y = acc[mt][nt][3] * mk1;
            *(float2*)&C[(size_t)r0 * D_ATTN + col] = o0;
            *(float2*)&C[(size_t)(r0 + 8) * D_ATTN + col] = o1;
        }
    }
}

// ----------------------------------------------------------------------------
// fp32 -> bf16 hi/lo split (vectorized by 4)
// ----------------------------------------------------------------------------
__global__ void split_kernel(const float4* __restrict__ x,
                             __nv_bfloat16* __restrict__ hi,
                             __nv_bfloat16* __restrict__ lo, int n4)
{
    int i = blockIdx.x * 256 + threadIdx.x;
    if (i >= n4) return;
    float4 v = x[i];
    __nv_bfloat16 h0 = __float2bfloat16(v.x);
    __nv_bfloat16 h1 = __float2bfloat16(v.y);
    __nv_bfloat16 h2 = __float2bfloat16(v.z);
    __nv_bfloat16 h3 = __float2bfloat16(v.w);
    __nv_bfloat16 l0 = __float2bfloat16(v.x - __bfloat162float(h0));
    __nv_bfloat16 l1 = __float2bfloat16(v.y - __bfloat162float(h1));
    __nv_bfloat16 l2 = __float2bfloat16(v.z - __bfloat162float(h2));
    __nv_bfloat16 l3 = __float2bfloat16(v.w - __bfloat162float(h3));
    uint2 oh, ol;
    oh.x = (uint32_t)__bfloat16_as_ushort(h0) | ((uint32_t)__bfloat16_as_ushort(h1) << 16);
    oh.y = (uint32_t)__bfloat16_as_ushort(h2) | ((uint32_t)__bfloat16_as_ushort(h3) << 16);
    ol.x = (uint32_t)__bfloat16_as_ushort(l0) | ((uint32_t)__bfloat16_as_ushort(l1) << 16);
    ol.y = (uint32_t)__bfloat16_as_ushort(l2) | ((uint32_t)__bfloat16_as_ushort(l3) << 16);
    *(uint2*)(hi + (size_t)i * 4) = oh;
    *(uint2*)(lo + (size_t)i * 4) = ol;
}

// ----------------------------------------------------------------------------
// Tiled transpose + split: W[K,N] -> Wt_hi/lo[N,K].
// 32x32 tile via smem: coalesced 128B reads, conflict-free smem, coalesced
// 64B bf16 row writes (replaces the old fully-scattered 2-byte writes).
// grid = (N/32, K/32), 256 threads (32x8).
// ----------------------------------------------------------------------------
__global__ void splitT_kernel(const float* __restrict__ W,
                              __nv_bfloat16* __restrict__ hiT,
                              __nv_bfloat16* __restrict__ loT, int K, int N)
{
    __shared__ float tile[32][33];
    const int tx = threadIdx.x & 31;
    const int ty = threadIdx.x >> 5;       // 0..7
    const int n0 = blockIdx.x * 32;
    const int k0 = blockIdx.y * 32;

#pragma unroll
    for (int i = 0; i < 4; i++)
        tile[ty + i * 8][tx] = W[(size_t)(k0 + ty + i * 8) * N + n0 + tx];
    __syncthreads();

#pragma unroll
    for (int i = 0; i < 4; i++) {
        int n = ty + i * 8;                 // local n
        float v = tile[tx][n];              // [k_local][n_local] — stride-33, conflict-free
        __nv_bfloat16 h = __float2bfloat16(v);
        __nv_bfloat16 l = __float2bfloat16(v - __bfloat162float(h));
        hiT[(size_t)(n0 + n) * K + k0 + tx] = h;
        loT[(size_t)(n0 + n) * K + k0 + tx] = l;
    }
}

// ----------------------------------------------------------------------------
// Fused attention per (b, h): register-blocked, 8 query rows per warp-iteration.
// ----------------------------------------------------------------------------
#define ATT_F_KS 0
#define ATT_F_VS 5440
#define ATT_F_GT 10880
#define ATT_F_QG 10976
#define ATT_F_AR 15072
#define ATT_SMEM ((15072 + 5440) * 4)   // 82048 bytes

__global__ void __launch_bounds__(256, 2)
attention_kernel(const float* __restrict__ Q,
                 const float* __restrict__ K,
                 const float* __restrict__ V,
                 const float* __restrict__ conf,
                 const int* __restrict__ pmask,
                 const float* __restrict__ conf_w,
                 const float* __restrict__ conf_b,
                 float* __restrict__ attn_out,
                 __nv_bfloat16* __restrict__ ctx_hi,
                 __nv_bfloat16* __restrict__ ctx_lo)
{
    extern __shared__ float sf[];
    float* Ks = sf + ATT_F_KS;
    float* Vs = sf + ATT_F_VS;
    float* gt = sf + ATT_F_GT;
    float* Qg = sf + ATT_F_QG;
    float* Ar = sf + ATT_F_AR;

    const int h = blockIdx.x;
    const int b = blockIdx.y;
    const int tid = threadIdx.x;
    const int warp = tid >> 5;
    const int lane = tid & 31;

    if (tid < PP) {
        if (pmask[b * PP + tid]) {
            gt[tid] = -INFINITY;
        } else {
            float x = conf[b * PP + tid] * conf_w[0] + conf_b[0];
            float s = 1.0f / (1.0f + __expf(-x));
            gt[tid] = fmaxf(logf(s), -10.0f);
        }
    }
    for (int i = tid; i < PP * DH; i += 256) {
        int p = i / DH, d = i % DH;
        Ks[d * PP + p] = K[((size_t)(b * PP + p)) * D_ATTN + h * DH + d];
        Vs[i]          = V[((size_t)(b * PP + p)) * D_ATTN + h * DH + d];
    }
    __syncthreads();

    const bool v2 = lane < (PP - 64);
    const float g0 = gt[lane];
    const float g1 = gt[lane + 32];
    const float g2 = v2 ? gt[lane + 64] : -INFINITY;

    float* Qw = Qg + warp * 512;
    float* Aw = Ar + warp * 680;

#pragma unroll
    for (int grp = 0; grp < 2; grp++) {
        const int rbase = warp * 8 + grp * 64;

#pragma unroll
        for (int t = 0; t < 4; t++) {
            int idx = t * 128 + lane * 4;
            int r = idx >> 6, d = idx & 63;
            *(float4*)&Qw[idx] =
                *(const float4*)&Q[((size_t)(b * NN + rbase + r)) * D_ATTN + h * DH + d];
        }
        __syncwarp();

        float l[8][3];
#pragma unroll
        for (int r = 0; r < 8; r++) { l[r][0] = 0.0f; l[r][1] = 0.0f; l[r][2] = 0.0f; }

#pragma unroll 4
        for (int d = 0; d < DH; d++) {
            const float* kd = &Ks[d * PP];
            float k0 = kd[lane];
            float k1 = kd[lane + 32];
            float k2 = kd[v2 ? (lane + 64) : 0];
#pragma unroll
            for (int r = 0; r < 8; r++) {
                float q = Qw[r * 64 + d];
                l[r][0] = fmaf(q, k0, l[r][0]);
                l[r][1] = fmaf(q, k1, l[r][1]);
                l[r][2] = fmaf(q, k2, l[r][2]);
            }
        }

        float* aout = &attn_out[(((size_t)(b * HH + h)) * NN + rbase) * PP];
#pragma unroll
        for (int r = 0; r < 8; r++) {
            float l0 = l[r][0] * 0.125f + g0;
            float l1 = l[r][1] * 0.125f + g1;
            float l2 = v2 ? (l[r][2] * 0.125f + g2) : -INFINITY;

            float m = fmaxf(l0, fmaxf(l1, l2));
#pragma unroll
            for (int o = 16; o > 0; o >>= 1)
                m = fmaxf(m, __shfl_xor_sync(0xFFFFFFFF, m, o));

            float e0, e1, e2;
            if (isinf(m) && m < 0.0f) {
                e0 = e1 = e2 = 0.0f;
            } else {
                e0 = expf(l0 - m);
                e1 = expf(l1 - m);
                e2 = v2 ? expf(l2 - m) : 0.0f;
            }
            float s = e0 + e1 + e2;
#pragma unroll
            for (int o = 16; o > 0; o >>= 1)
                s += __shfl_xor_sync(0xFFFFFFFF, s, o);
            float inv = (s > 0.0f) ? (1.0f / s) : 0.0f;

            float a0 = e0 * inv, a1 = e1 * inv;
            Aw[r * PP + lane] = a0;
            aout[r * PP + lane] = a0;
            Aw[r * PP + lane + 32] = a1;
            aout[r * PP + lane + 32] = a1;
            if (v2) {
                float a2 = e2 * inv;
                Aw[r * PP + lane + 64] = a2;
                aout[r * PP + lane + 64] = a2;
            }
        }
        __syncwarp();

        float c0[8], c1[8];
#pragma unroll
        for (int r = 0; r < 8; r++) { c0[r] = 0.0f; c1[r] = 0.0f; }

#pragma unroll 5
        for (int p = 0; p < PP; p++) {
            float vv0 = Vs[p * DH + lane];
            float vv1 = Vs[p * DH + lane + 32];
#pragma unroll
            for (int r = 0; r < 8; r++) {
                float a = Aw[r * PP + p];
                c0[r] = fmaf(a, vv0, c0[r]);
                c1[r] = fmaf(a, vv1, c1[r]);
            }
        }

#pragma unroll
        for (int r = 0; r < 8; r++) {
            size_t base = ((size_t)(b * NN + rbase + r)) * D_ATTN + h * DH;
            __nv_bfloat16 h0 = __float2bfloat16(c0[r]);
            __nv_bfloat16 h1 = __float2bfloat16(c1[r]);
            ctx_hi[base + lane]      = h0;
            ctx_hi[base + lane + 32] = h1;
            ctx_lo[base + lane]      = __float2bfloat16(c0[r] - __bfloat162float(h0));
            ctx_lo[base + lane + 32] = __float2bfloat16(c1[r] - __bfloat162float(h1));
        }
        __syncwarp();
    }
}

// ----------------------------------------------------------------------------
extern "C" void kernel_launch(void* const* d_in, const int* in_sizes, int n_in,
                              void* d_out, int out_size)
{
    const float* ligand  = (const float*)d_in[0];
    const float* protein = (const float*)d_in[1];
    const float* conf    = (const float*)d_in[2];
    const int*   pmask   = (const int*)d_in[3];
    const int*   lmask   = (const int*)d_in[4];
    const float* Wq = (const float*)d_in[5];
    const float* Wk = (const float*)d_in[6];
    const float* Wv = (const float*)d_in[7];
    const float* Wo = (const float*)d_in[8];
    const float* conf_w = (const float*)d_in[9];
    const float* conf_b = (const float*)d_in[10];

    float* out_main = (float*)d_out;                          // (B,N,D_ATTN)
    float* out_attn = out_main + (size_t)BB * NN * D_ATTN;    // (B,H,N,P)

    float *Q, *Kb, *Vb;
    cudaGetSymbolAddress((void**)&Q,  g_Q);
    cudaGetSymbolAddress((void**)&Kb, g_K);
    cudaGetSymbolAddress((void**)&Vb, g_V);

    __nv_bfloat16 *lig_hi, *lig_lo, *prot_hi, *prot_lo, *ctx_hi, *ctx_lo;
    __nv_bfloat16 *Wqt_hi, *Wqt_lo, *Wkt_hi, *Wkt_lo, *Wvt_hi, *Wvt_lo, *Wot_hi, *Wot_lo;
    cudaGetSymbolAddress((void**)&lig_hi,  g_lig_hi);
    cudaGetSymbolAddress((void**)&lig_lo,  g_lig_lo);
    cudaGetSymbolAddress((void**)&prot_hi, g_prot_hi);
    cudaGetSymbolAddress((void**)&prot_lo, g_prot_lo);
    cudaGetSymbolAddress((void**)&ctx_hi,  g_ctx_hi);
    cudaGetSymbolAddress((void**)&ctx_lo,  g_ctx_lo);
    cudaGetSymbolAddress((void**)&Wqt_hi,  g_Wqt_hi);
    cudaGetSymbolAddress((void**)&Wqt_lo,  g_Wqt_lo);
    cudaGetSymbolAddress((void**)&Wkt_hi,  g_Wkt_hi);
    cudaGetSymbolAddress((void**)&Wkt_lo,  g_Wkt_lo);
    cudaGetSymbolAddress((void**)&Wvt_hi,  g_Wvt_hi);
    cudaGetSymbolAddress((void**)&Wvt_lo,  g_Wvt_lo);
    cudaGetSymbolAddress((void**)&Wot_hi,  g_Wot_hi);
    cudaGetSymbolAddress((void**)&Wot_lo,  g_Wot_lo);

    cudaFuncSetAttribute(gemm_mma_kernel,
                         cudaFuncAttributeMaxDynamicSharedMemorySize, GT_SMEM);
    cudaFuncSetAttribute(attention_kernel,
                         cudaFuncAttributeMaxDynamicSharedMemorySize, ATT_SMEM);

    // weight transpose + split (tiled, coalesced)
    {
        dim3 g1(D_ATTN / 32, D_LIG / 32);
        splitT_kernel<<<g1, 256>>>(Wq, Wqt_hi, Wqt_lo, D_LIG,  D_ATTN);
        dim3 g2(D_ATTN / 32, D_PROT / 32);
        splitT_kernel<<<g2, 256>>>(Wk, Wkt_hi, Wkt_lo, D_PROT, D_ATTN);
        splitT_kernel<<<g2, 256>>>(Wv, Wvt_hi, Wvt_lo, D_PROT, D_ATTN);
        dim3 g3(D_ATTN / 32, D_ATTN / 32);
        splitT_kernel<<<g3, 256>>>(Wo, Wot_hi, Wot_lo, D_ATTN, D_ATTN);
    }

    // activation splits
    {
        int n4 = (BB * NN * D_LIG) / 4;
        split_kernel<<<(n4 + 255) / 256, 256>>>((const float4*)ligand, lig_hi, lig_lo, n4);
    }
    {
        int n4 = (BB * PP * D_PROT) / 4;
        split_kernel<<<(n4 + 255) / 256, 256>>>((const float4*)protein, prot_hi, prot_lo, n4);
    }

    // Q = ligand @ Wq (masked rows zeroed)
    {
        dim3 grid(D_ATTN / GBN, (BB * NN) / GBM);
        gemm_mma_kernel<<<grid, 256, GT_SMEM>>>(lig_hi, lig_lo, Wqt_hi, Wqt_lo,
                                                Q, D_LIG, lmask);
    }
    // K, V = protein @ Wk/Wv
    {
        dim3 grid(D_ATTN / GBN, (BB * PP) / GBM);
        gemm_mma_kernel<<<grid, 256, GT_SMEM>>>(prot_hi, prot_lo, Wkt_hi, Wkt_lo,
                                                Kb, D_PROT, nullptr);
        gemm_mma_kernel<<<grid, 256, GT_SMEM>>>(prot_hi, prot_lo, Wvt_hi, Wvt_lo,
                                                Vb, D_PROT, nullptr);
    }
    // attention (writes attn probs + ctx bf16 hi/lo directly)
    {
        dim3 grid(HH, BB);
        attention_kernel<<<grid, 256, ATT_SMEM>>>(Q, Kb, Vb, conf, pmask, conf_w, conf_b,
                                                  out_attn, ctx_hi, ctx_lo);
    }
    // out = ctx @ Wo (masked rows zeroed)
    {
        dim3 grid(D_ATTN / GBN, (BB * NN) / GBM);
        gemm_mma_kernel<<<grid, 256, GT_SMEM>>>(ctx_hi, ctx_lo, Wot_hi, Wot_lo,
                                                out_main, D_ATTN, lmask);
    }
}